// round 7
// baseline (speedup 1.0000x reference)
#include <cuda_runtime.h>
#include <math.h>

#define NB 8
#define NH 16
#define ND 1024
#define NHD 64
#define NPAST 8192
#define NBH (NB*NH)                   // 128
#define KEYS_PER_WARP 32
#define WARPS_PB 8
#define KEYS_PB (KEYS_PER_WARP*WARPS_PB)  // 256 keys per block
#define NCHUNK (NPAST/KEYS_PB)            // 32 block-chunks per (b,h)
#define LN10000 9.210340371976184f

// Scratch (allocation-free: __device__ globals)
__device__ float g_qkv[3*NB*ND];            // q | k_new | v_new (bias applied)
__device__ float g_m[NBH*NCHUNK];
__device__ float g_l[NBH*NCHUNK];
__device__ float g_acc[NBH*NCHUNK*NHD];     // 1 MB
__device__ float g_ctx[NB*ND];
__device__ float g_warm_sink[1024];

// ---------------------------------------------------------------------------
// Kernel A1: Q projection, block-per-row.  grid 1024, 256 thr.
// ---------------------------------------------------------------------------
__global__ void proj_q_kernel(const float* __restrict__ x,
                              const float* __restrict__ Wq,
                              const float* __restrict__ bq) {
    const int row = blockIdx.x;
    const int warp = threadIdx.x >> 5, lane = threadIdx.x & 31;
    const int c4 = warp*32 + lane;

    const float4 w4 = ((const float4*)(Wq + (size_t)row * ND))[c4];
    const float4* x4p = (const float4*)x;

    float acc[NB];
#pragma unroll
    for (int b = 0; b < NB; ++b) {
        const float4 x4 = __ldg(x4p + b*(ND/4) + c4);
        acc[b] = w4.x*x4.x + w4.y*x4.y + w4.z*x4.z + w4.w*x4.w;
    }
#pragma unroll
    for (int b = 0; b < NB; ++b) {
#pragma unroll
        for (int o = 16; o; o >>= 1) acc[b] += __shfl_xor_sync(0xffffffffu, acc[b], o);
    }
    __shared__ float sm[8][NB+1];
    if (lane == 0) {
#pragma unroll
        for (int b = 0; b < NB; ++b) sm[warp][b] = acc[b];
    }
    __syncthreads();
    if (threadIdx.x < NB) {
        const int b = threadIdx.x;
        float v = sm[0][b];
#pragma unroll
        for (int w = 1; w < 8; ++w) v += sm[w][b];
        g_qkv[b*ND + row] = v + bq[row];
    }
}

// ---------------------------------------------------------------------------
// Kernel A2: K/V projection (runs on side stream under attn_partial).
// grid 2048, 256 thr.  r<1024 -> K row, else V row.
// ---------------------------------------------------------------------------
__global__ void proj_kv_kernel(const float* __restrict__ x,
                               const float* __restrict__ Wk, const float* __restrict__ bk,
                               const float* __restrict__ Wv, const float* __restrict__ bv) {
    const int r = blockIdx.x;
    const int which = r >> 10;                      // 0=k 1=v
    const int row = r & 1023;
    const float* W    = which ? Wv : Wk;
    const float* bias = which ? bv : bk;

    const int warp = threadIdx.x >> 5, lane = threadIdx.x & 31;
    const int c4 = warp*32 + lane;

    const float4 w4 = ((const float4*)(W + (size_t)row * ND))[c4];
    const float4* x4p = (const float4*)x;

    float acc[NB];
#pragma unroll
    for (int b = 0; b < NB; ++b) {
        const float4 x4 = __ldg(x4p + b*(ND/4) + c4);
        acc[b] = w4.x*x4.x + w4.y*x4.y + w4.z*x4.z + w4.w*x4.w;
    }
#pragma unroll
    for (int b = 0; b < NB; ++b) {
#pragma unroll
        for (int o = 16; o; o >>= 1) acc[b] += __shfl_xor_sync(0xffffffffu, acc[b], o);
    }
    __shared__ float sm[8][NB+1];
    if (lane == 0) {
#pragma unroll
        for (int b = 0; b < NB; ++b) sm[warp][b] = acc[b];
    }
    __syncthreads();
    if (threadIdx.x < NB) {
        const int b = threadIdx.x;
        float v = sm[0][b];
#pragma unroll
        for (int w = 1; w < 8; ++w) v += sm[w][b];
        g_qkv[(1 + which)*NB*ND + b*ND + row] = v + bias[row];
    }
}

// ---------------------------------------------------------------------------
// Kernel A3: warm Wo into L2 (evict-normal reads) while attn_partial streams.
// grid 1024, 256 thr.  Deterministic sink write defeats DCE.
// ---------------------------------------------------------------------------
__global__ void warm_wo_kernel(const float* __restrict__ Wo) {
    const float4 w4 = ((const float4*)(Wo + (size_t)blockIdx.x * ND))[threadIdx.x];
    float s = w4.x + w4.y + w4.z + w4.w;
#pragma unroll
    for (int o = 16; o; o >>= 1) s += __shfl_xor_sync(0xffffffffu, s, o);
    __shared__ float sm[8];
    if ((threadIdx.x & 31) == 0) sm[threadIdx.x >> 5] = s;
    __syncthreads();
    if (threadIdx.x == 0) {
        float v = 0.f;
#pragma unroll
        for (int w = 0; w < 8; ++w) v += sm[w];
        g_warm_sink[blockIdx.x] = v;
    }
}

// ---------------------------------------------------------------------------
// Kernel B: flash-decoding partials.  grid (NCHUNK, NBH), 256 thr (8 warps).
// RoPE(q) fused.  float4 loads: lanes 0-15 own key 2j, lanes 16-31 key 2j+1.
// ---------------------------------------------------------------------------
__global__ void attn_partial(const float* __restrict__ past_k,
                             const float* __restrict__ past_v) {
    const int bh   = blockIdx.y;
    const int warp = threadIdx.x >> 5, lane = threadIdx.x & 31;
    const int b = bh >> 4, h = bh & 15;

    __shared__ float qs[NHD];
    __shared__ float sm_m[WARPS_PB], sm_l[WARPS_PB];
    __shared__ float sm_acc[WARPS_PB][NHD];

    if (threadIdx.x < 32) {
        const int i = threadIdx.x;                  // freq index 0..31
        const float inv = expf(-((float)(2*i) / (float)NHD) * LN10000);
        float sn, cs; sincosf((float)NPAST * inv, &sn, &cs);
        const float* gq = g_qkv + b*ND + h*NHD;
        const float q1 = gq[i], q2 = gq[i+32];
        qs[i]    = q1*cs - q2*sn;
        qs[i+32] = q2*cs + q1*sn;
    }
    __syncthreads();

    const int l16 = lane & 15;
    const float4 q4 = ((const float4*)qs)[l16];

    const int wchunk = blockIdx.x * WARPS_PB + warp;   // 0..255
    const size_t off = ((size_t)bh * NPAST + (size_t)wchunk * KEYS_PER_WARP) * NHD;
    const float4* kb = (const float4*)(past_k + off);
    const float4* vb = (const float4*)(past_v + off);

    float m = -1e30f, l = 0.f;
    float4 acc = make_float4(0.f, 0.f, 0.f, 0.f);

#pragma unroll 4
    for (int j = 0; j < KEYS_PER_WARP/2; ++j) {
        const float4 k4 = __ldcs(kb + j*32 + lane);    // 2 key rows / warp
        const float4 v4 = __ldcs(vb + j*32 + lane);
        float s = q4.x*k4.x + q4.y*k4.y + q4.z*k4.z + q4.w*k4.w;
        s += __shfl_xor_sync(0xffffffffu, s, 1);
        s += __shfl_xor_sync(0xffffffffu, s, 2);
        s += __shfl_xor_sync(0xffffffffu, s, 4);
        s += __shfl_xor_sync(0xffffffffu, s, 8);
        s *= 0.125f;                                   // 1/sqrt(64)
        const float nm = fmaxf(m, s);
        const float f  = __expf(m - nm);
        const float p  = __expf(s - nm);
        acc.x = acc.x*f + p*v4.x;
        acc.y = acc.y*f + p*v4.y;
        acc.z = acc.z*f + p*v4.z;
        acc.w = acc.w*f + p*v4.w;
        l = l*f + p;
        m = nm;
    }

    // Merge the two half-warp streams (even keys / odd keys).
    const float mo = __shfl_xor_sync(0xffffffffu, m, 16);
    const float lo = __shfl_xor_sync(0xffffffffu, l, 16);
    float4 ao;
    ao.x = __shfl_xor_sync(0xffffffffu, acc.x, 16);
    ao.y = __shfl_xor_sync(0xffffffffu, acc.y, 16);
    ao.z = __shfl_xor_sync(0xffffffffu, acc.z, 16);
    ao.w = __shfl_xor_sync(0xffffffffu, acc.w, 16);
    const float M  = fmaxf(m, mo);
    const float wa = __expf(m - M), wb = __expf(mo - M);
    float4 comb;
    comb.x = acc.x*wa + ao.x*wb;
    comb.y = acc.y*wa + ao.y*wb;
    comb.z = acc.z*wa + ao.z*wb;
    comb.w = acc.w*wa + ao.w*wb;
    const float L = l*wa + lo*wb;

    if (lane < 16) ((float4*)sm_acc[warp])[l16] = comb;
    if (lane == 0) { sm_m[warp] = M; sm_l[warp] = L; }
    __syncthreads();

    // First 64 threads combine the 8 warp partials -> one block partial.
    if (threadIdx.x < NHD) {
        const int d = threadIdx.x;
        float Mb = sm_m[0];
#pragma unroll
        for (int w = 1; w < WARPS_PB; ++w) Mb = fmaxf(Mb, sm_m[w]);
        float Lb = 0.f, a = 0.f;
#pragma unroll
        for (int w = 0; w < WARPS_PB; ++w) {
            const float wg = __expf(sm_m[w] - Mb);
            a  += sm_acc[w][d] * wg;
            Lb += sm_l[w] * wg;
        }
        const int idx = bh*NCHUNK + blockIdx.x;
        g_acc[idx*NHD + d] = a;
        if (d == 0) { g_m[idx] = Mb; g_l[idx] = Lb; }
    }
}

// ---------------------------------------------------------------------------
// Kernel C: combine 32 block partials per (b,h) + fold in the new key/value
// (RoPE(k_new) fused).  grid NBH, 256 thr.
// ---------------------------------------------------------------------------
__global__ void attn_reduce() {
    const int bh  = blockIdx.x;
    const int tid = threadIdx.x;
    const int c = tid >> 6, d = tid & 63;
    const int b = bh >> 4, h = bh & 15;

    __shared__ float qs[NHD], ks[NHD];
    __shared__ float s_acc[4][NHD];
    __shared__ float s_l[4];
    __shared__ float red[NHD];
    __shared__ float s_dot;

    if (tid < 32) {
        const int i = tid;
        const float inv = expf(-((float)(2*i) / (float)NHD) * LN10000);
        float sn, cs; sincosf((float)NPAST * inv, &sn, &cs);
        const float* gq = g_qkv + b*ND + h*NHD;
        const float* gk = g_qkv + NB*ND + b*ND + h*NHD;
        const float q1 = gq[i], q2 = gq[i+32];
        qs[i]    = q1*cs - q2*sn;
        qs[i+32] = q2*cs + q1*sn;
        const float k1 = gk[i], k2 = gk[i+32];
        ks[i]    = k1*cs - k2*sn;
        ks[i+32] = k2*cs + k1*sn;
    }
    __syncthreads();

    const float* mptr = g_m + bh*NCHUNK;
    const float* lptr = g_l + bh*NCHUNK;
    const float* aptr = g_acc + (size_t)bh*NCHUNK*NHD;

    float M = -1e30f;
#pragma unroll
    for (int i = 0; i < NCHUNK; ++i) M = fmaxf(M, mptr[i]);

    float L = 0.f, a = 0.f;
#pragma unroll
    for (int i = c; i < NCHUNK; i += 4) {
        const float w = __expf(mptr[i] - M);
        L += lptr[i] * w;
        a += aptr[i*NHD + d] * w;
    }
    s_acc[c][d] = a;
    if (d == 0) s_l[c] = L;

    if (tid < NHD) red[tid] = qs[tid] * ks[tid];
    __syncthreads();

    if (tid < 32) {
        float v = red[tid] + red[tid + 32];
#pragma unroll
        for (int o = 16; o; o >>= 1) v += __shfl_xor_sync(0xffffffffu, v, o);
        if (tid == 0) s_dot = v * 0.125f;          // score of the new key
    }
    __syncthreads();

    if (tid < NHD) {
        float A  = s_acc[0][d] + s_acc[1][d] + s_acc[2][d] + s_acc[3][d];
        float Lt = s_l[0] + s_l[1] + s_l[2] + s_l[3];
        const float s_new = s_dot;
        const float M2 = fmaxf(M, s_new);
        const float w0 = __expf(M - M2);
        const float p  = __expf(s_new - M2);
        const float vd = g_qkv[2*NB*ND + b*ND + h*NHD + d];
        A  = A*w0 + p*vd;
        Lt = Lt*w0 + p;
        g_ctx[b*ND + h*NHD + d] = A / Lt;
    }
}

// ---------------------------------------------------------------------------
// Kernel D: output projection, block-per-row (Wo expected L2-warm).
// ---------------------------------------------------------------------------
__global__ void outproj_kernel(const float* __restrict__ Wo,
                               const float* __restrict__ bo,
                               float* __restrict__ out) {
    const int r = blockIdx.x;                       // 0..1023
    const int warp = threadIdx.x >> 5, lane = threadIdx.x & 31;
    const int c4 = warp*32 + lane;

    const float4 w4 = ((const float4*)(Wo + (size_t)r * ND))[c4];
    const float4* cp = (const float4*)g_ctx;

    float acc[NB];
#pragma unroll
    for (int b = 0; b < NB; ++b) {
        const float4 c4v = cp[b*(ND/4) + c4];
        acc[b] = w4.x*c4v.x + w4.y*c4v.y + w4.z*c4v.z + w4.w*c4v.w;
    }
#pragma unroll
    for (int b = 0; b < NB; ++b) {
#pragma unroll
        for (int o = 16; o; o >>= 1) acc[b] += __shfl_xor_sync(0xffffffffu, acc[b], o);
    }
    __shared__ float sm[8][NB+1];
    if (lane == 0) {
#pragma unroll
        for (int b = 0; b < NB; ++b) sm[warp][b] = acc[b];
    }
    __syncthreads();
    if (threadIdx.x < NB) {
        const int b = threadIdx.x;
        float v = sm[0][b];
#pragma unroll
        for (int w = 1; w < 8; ++w) v += sm[w][b];
        out[b*ND + r] = v + bo[r];
    }
}

// ---------------------------------------------------------------------------
extern "C" void kernel_launch(void* const* d_in, const int* in_sizes, int n_in,
                              void* d_out, int out_size) {
    const float* x      = (const float*)d_in[0];
    const float* Wq     = (const float*)d_in[1];
    const float* bq     = (const float*)d_in[2];
    const float* Wk     = (const float*)d_in[3];
    const float* bk     = (const float*)d_in[4];
    const float* Wv     = (const float*)d_in[5];
    const float* bv     = (const float*)d_in[6];
    const float* Wo     = (const float*)d_in[7];
    const float* bo     = (const float*)d_in[8];
    const float* past_k = (const float*)d_in[9];
    const float* past_v = (const float*)d_in[10];
    float* out = (float*)d_out;

    // One-time side stream + fork/join events (host objects only; no device mem).
    static cudaStream_t s_side = nullptr;
    static cudaEvent_t  e_fork = nullptr, e_join = nullptr;
    if (s_side == nullptr) {
        cudaStreamCreateWithFlags(&s_side, cudaStreamNonBlocking);
        cudaEventCreateWithFlags(&e_fork, cudaEventDisableTiming);
        cudaEventCreateWithFlags(&e_join, cudaEventDisableTiming);
    }

    // Fork: side stream handles K/V projection + Wo L2-warm, overlapped with
    // the DRAM-bound attention scan on the main (legacy) stream.
    cudaEventRecord(e_fork, 0);
    cudaStreamWaitEvent(s_side, e_fork, 0);

    proj_q_kernel<<<ND, 256>>>(x, Wq, bq);                          // main
    proj_kv_kernel<<<2*ND, 256, 0, s_side>>>(x, Wk, bk, Wv, bv);    // side
    warm_wo_kernel<<<ND, 256, 0, s_side>>>(Wo);                     // side
    attn_partial<<<dim3(NCHUNK, NBH), 256>>>(past_k, past_v);       // main

    // Join: reduce needs k_new/v_new from the side stream.
    cudaEventRecord(e_join, s_side);
    cudaStreamWaitEvent(0, e_join, 0);

    attn_reduce<<<NBH, 256>>>();
    outproj_kernel<<<ND, 256>>>(Wo, bo, out);
}

// round 8
// speedup vs baseline: 1.0443x; 1.0443x over previous
#include <cuda_runtime.h>
#include <math.h>

#define NB 8
#define NH 16
#define ND 1024
#define NHD 64
#define NPAST 8192
#define NBH (NB*NH)                   // 128
#define KEYS_PER_WARP 32
#define WARPS_PB 8
#define KEYS_PB (KEYS_PER_WARP*WARPS_PB)  // 256 keys per block
#define NCHUNK (NPAST/KEYS_PB)            // 32 block-chunks per (b,h)
#define NITER (KEYS_PER_WARP/2)           // 16 iterations (2 keys each)
#define LN10000 9.210340371976184f

// Scratch (allocation-free: __device__ globals)
__device__ float g_qkv[3*NB*ND];            // q | k_new | v_new (bias applied)
__device__ float g_m[NBH*NCHUNK];
__device__ float g_l[NBH*NCHUNK];
__device__ float g_acc[NBH*NCHUNK*NHD];     // 1 MB
__device__ float g_ctx[NB*ND];

// ---------------------------------------------------------------------------
// Kernel A1: Q projection, block-per-row.  grid 1024, 256 thr.
// ---------------------------------------------------------------------------
__global__ void proj_q_kernel(const float* __restrict__ x,
                              const float* __restrict__ Wq,
                              const float* __restrict__ bq) {
    const int row = blockIdx.x;
    const int warp = threadIdx.x >> 5, lane = threadIdx.x & 31;
    const int c4 = warp*32 + lane;

    const float4 w4 = ((const float4*)(Wq + (size_t)row * ND))[c4];
    const float4* x4p = (const float4*)x;

    float acc[NB];
#pragma unroll
    for (int b = 0; b < NB; ++b) {
        const float4 x4 = __ldg(x4p + b*(ND/4) + c4);
        acc[b] = w4.x*x4.x + w4.y*x4.y + w4.z*x4.z + w4.w*x4.w;
    }
#pragma unroll
    for (int b = 0; b < NB; ++b) {
#pragma unroll
        for (int o = 16; o; o >>= 1) acc[b] += __shfl_xor_sync(0xffffffffu, acc[b], o);
    }
    __shared__ float sm[8][NB+1];
    if (lane == 0) {
#pragma unroll
        for (int b = 0; b < NB; ++b) sm[warp][b] = acc[b];
    }
    __syncthreads();
    if (threadIdx.x < NB) {
        const int b = threadIdx.x;
        float v = sm[0][b];
#pragma unroll
        for (int w = 1; w < 8; ++w) v += sm[w][b];
        g_qkv[b*ND + row] = v + bq[row];
    }
}

// ---------------------------------------------------------------------------
// Kernel A2: K/V projection (runs on side stream under attn_partial).
// grid 2048, 256 thr.  r<1024 -> K row, else V row.
// ---------------------------------------------------------------------------
__global__ void proj_kv_kernel(const float* __restrict__ x,
                               const float* __restrict__ Wk, const float* __restrict__ bk,
                               const float* __restrict__ Wv, const float* __restrict__ bv) {
    const int r = blockIdx.x;
    const int which = r >> 10;                      // 0=k 1=v
    const int row = r & 1023;
    const float* W    = which ? Wv : Wk;
    const float* bias = which ? bv : bk;

    const int warp = threadIdx.x >> 5, lane = threadIdx.x & 31;
    const int c4 = warp*32 + lane;

    const float4 w4 = ((const float4*)(W + (size_t)row * ND))[c4];
    const float4* x4p = (const float4*)x;

    float acc[NB];
#pragma unroll
    for (int b = 0; b < NB; ++b) {
        const float4 x4 = __ldg(x4p + b*(ND/4) + c4);
        acc[b] = w4.x*x4.x + w4.y*x4.y + w4.z*x4.z + w4.w*x4.w;
    }
#pragma unroll
    for (int b = 0; b < NB; ++b) {
#pragma unroll
        for (int o = 16; o; o >>= 1) acc[b] += __shfl_xor_sync(0xffffffffu, acc[b], o);
    }
    __shared__ float sm[8][NB+1];
    if (lane == 0) {
#pragma unroll
        for (int b = 0; b < NB; ++b) sm[warp][b] = acc[b];
    }
    __syncthreads();
    if (threadIdx.x < NB) {
        const int b = threadIdx.x;
        float v = sm[0][b];
#pragma unroll
        for (int w = 1; w < 8; ++w) v += sm[w][b];
        g_qkv[(1 + which)*NB*ND + b*ND + row] = v + bias[row];
    }
}

// ---------------------------------------------------------------------------
// Kernel B: flash-decoding partials, TWO-PHASE per warp chunk.
// grid (NCHUNK, NBH), 256 thr (8 warps).  RoPE(q) fused.
// Phase 1: 16 independent K loads -> scores in registers (max MLP).
// Phase 2: softmax of the 16 scores, then 16 independent V loads -> acc.
// Lanes 0-15 own even keys, lanes 16-31 odd keys; halves merged at the end.
// ---------------------------------------------------------------------------
__global__ void attn_partial(const float* __restrict__ past_k,
                             const float* __restrict__ past_v) {
    const int bh   = blockIdx.y;
    const int warp = threadIdx.x >> 5, lane = threadIdx.x & 31;
    const int b = bh >> 4, h = bh & 15;

    __shared__ float qs[NHD];
    __shared__ float sm_m[WARPS_PB], sm_l[WARPS_PB];
    __shared__ float sm_acc[WARPS_PB][NHD];

    if (threadIdx.x < 32) {
        const int i = threadIdx.x;                  // freq index 0..31
        const float inv = expf(-((float)(2*i) / (float)NHD) * LN10000);
        float sn, cs; sincosf((float)NPAST * inv, &sn, &cs);
        const float* gq = g_qkv + b*ND + h*NHD;
        const float q1 = gq[i], q2 = gq[i+32];
        qs[i]    = q1*cs - q2*sn;
        qs[i+32] = q2*cs + q1*sn;
    }
    __syncthreads();

    const int l16 = lane & 15;
    const float4 q4 = ((const float4*)qs)[l16];

    const int wchunk = blockIdx.x * WARPS_PB + warp;   // 0..255
    const size_t off = ((size_t)bh * NPAST + (size_t)wchunk * KEYS_PER_WARP) * NHD;
    const float4* kb = (const float4*)(past_k + off);
    const float4* vb = (const float4*)(past_v + off);

    // ---- Phase 1: scores.  16 fully independent K loads. ----
    float s[NITER];
#pragma unroll
    for (int j = 0; j < NITER; ++j) {
        const float4 k4 = __ldcs(kb + j*32 + lane);
        float t = q4.x*k4.x + q4.y*k4.y + q4.z*k4.z + q4.w*k4.w;
        t += __shfl_xor_sync(0xffffffffu, t, 1);
        t += __shfl_xor_sync(0xffffffffu, t, 2);
        t += __shfl_xor_sync(0xffffffffu, t, 4);
        t += __shfl_xor_sync(0xffffffffu, t, 8);
        s[j] = t * 0.125f;                          // 1/sqrt(64)
    }

    // ---- Softmax over this lane's 16 scores. ----
    float m = s[0];
#pragma unroll
    for (int j = 1; j < NITER; ++j) m = fmaxf(m, s[j]);
    float l = 0.f;
#pragma unroll
    for (int j = 0; j < NITER; ++j) { s[j] = __expf(s[j] - m); l += s[j]; }

    // ---- Phase 2: weighted V accumulation.  16 independent V loads. ----
    float4 acc0 = make_float4(0.f,0.f,0.f,0.f);
    float4 acc1 = make_float4(0.f,0.f,0.f,0.f);
#pragma unroll
    for (int j = 0; j < NITER; j += 2) {
        const float4 va = __ldcs(vb + j*32 + lane);
        const float4 vc = __ldcs(vb + (j+1)*32 + lane);
        acc0.x += s[j]*va.x;   acc0.y += s[j]*va.y;
        acc0.z += s[j]*va.z;   acc0.w += s[j]*va.w;
        acc1.x += s[j+1]*vc.x; acc1.y += s[j+1]*vc.y;
        acc1.z += s[j+1]*vc.z; acc1.w += s[j+1]*vc.w;
    }
    float4 acc;
    acc.x = acc0.x + acc1.x; acc.y = acc0.y + acc1.y;
    acc.z = acc0.z + acc1.z; acc.w = acc0.w + acc1.w;

    // ---- Merge the two half-warp streams (even keys / odd keys). ----
    const float mo = __shfl_xor_sync(0xffffffffu, m, 16);
    const float lo = __shfl_xor_sync(0xffffffffu, l, 16);
    float4 ao;
    ao.x = __shfl_xor_sync(0xffffffffu, acc.x, 16);
    ao.y = __shfl_xor_sync(0xffffffffu, acc.y, 16);
    ao.z = __shfl_xor_sync(0xffffffffu, acc.z, 16);
    ao.w = __shfl_xor_sync(0xffffffffu, acc.w, 16);
    const float M  = fmaxf(m, mo);
    const float wa = __expf(m - M), wb = __expf(mo - M);
    float4 comb;
    comb.x = acc.x*wa + ao.x*wb;
    comb.y = acc.y*wa + ao.y*wb;
    comb.z = acc.z*wa + ao.z*wb;
    comb.w = acc.w*wa + ao.w*wb;
    const float L = l*wa + lo*wb;

    if (lane < 16) ((float4*)sm_acc[warp])[l16] = comb;
    if (lane == 0) { sm_m[warp] = M; sm_l[warp] = L; }
    __syncthreads();

    // First 64 threads combine the 8 warp partials -> one block partial.
    if (threadIdx.x < NHD) {
        const int d = threadIdx.x;
        float Mb = sm_m[0];
#pragma unroll
        for (int w = 1; w < WARPS_PB; ++w) Mb = fmaxf(Mb, sm_m[w]);
        float Lb = 0.f, a = 0.f;
#pragma unroll
        for (int w = 0; w < WARPS_PB; ++w) {
            const float wg = __expf(sm_m[w] - Mb);
            a  += sm_acc[w][d] * wg;
            Lb += sm_l[w] * wg;
        }
        const int idx = bh*NCHUNK + blockIdx.x;
        g_acc[idx*NHD + d] = a;
        if (d == 0) { g_m[idx] = Mb; g_l[idx] = Lb; }
    }
}

// ---------------------------------------------------------------------------
// Kernel C: combine 32 block partials per (b,h) + fold in the new key/value
// (RoPE(k_new) fused).  grid NBH, 256 thr.
// ---------------------------------------------------------------------------
__global__ void attn_reduce() {
    const int bh  = blockIdx.x;
    const int tid = threadIdx.x;
    const int c = tid >> 6, d = tid & 63;
    const int b = bh >> 4, h = bh & 15;

    __shared__ float qs[NHD], ks[NHD];
    __shared__ float s_acc[4][NHD];
    __shared__ float s_l[4];
    __shared__ float red[NHD];
    __shared__ float s_dot;

    if (tid < 32) {
        const int i = tid;
        const float inv = expf(-((float)(2*i) / (float)NHD) * LN10000);
        float sn, cs; sincosf((float)NPAST * inv, &sn, &cs);
        const float* gq = g_qkv + b*ND + h*NHD;
        const float* gk = g_qkv + NB*ND + b*ND + h*NHD;
        const float q1 = gq[i], q2 = gq[i+32];
        qs[i]    = q1*cs - q2*sn;
        qs[i+32] = q2*cs + q1*sn;
        const float k1 = gk[i], k2 = gk[i+32];
        ks[i]    = k1*cs - k2*sn;
        ks[i+32] = k2*cs + k1*sn;
    }
    __syncthreads();

    const float* mptr = g_m + bh*NCHUNK;
    const float* lptr = g_l + bh*NCHUNK;
    const float* aptr = g_acc + (size_t)bh*NCHUNK*NHD;

    float M = -1e30f;
#pragma unroll
    for (int i = 0; i < NCHUNK; ++i) M = fmaxf(M, mptr[i]);

    float L = 0.f, a = 0.f;
#pragma unroll
    for (int i = c; i < NCHUNK; i += 4) {
        const float w = __expf(mptr[i] - M);
        L += lptr[i] * w;
        a += aptr[i*NHD + d] * w;
    }
    s_acc[c][d] = a;
    if (d == 0) s_l[c] = L;

    if (tid < NHD) red[tid] = qs[tid] * ks[tid];
    __syncthreads();

    if (tid < 32) {
        float v = red[tid] + red[tid + 32];
#pragma unroll
        for (int o = 16; o; o >>= 1) v += __shfl_xor_sync(0xffffffffu, v, o);
        if (tid == 0) s_dot = v * 0.125f;          // score of the new key
    }
    __syncthreads();

    if (tid < NHD) {
        float A  = s_acc[0][d] + s_acc[1][d] + s_acc[2][d] + s_acc[3][d];
        float Lt = s_l[0] + s_l[1] + s_l[2] + s_l[3];
        const float s_new = s_dot;
        const float M2 = fmaxf(M, s_new);
        const float w0 = __expf(M - M2);
        const float p  = __expf(s_new - M2);
        const float vd = g_qkv[2*NB*ND + b*ND + h*NHD + d];
        A  = A*w0 + p*vd;
        Lt = Lt*w0 + p;
        g_ctx[b*ND + h*NHD + d] = A / Lt;
    }
}

// ---------------------------------------------------------------------------
// Kernel D: output projection, block-per-row.  grid 1024, 256 thr.
// ---------------------------------------------------------------------------
__global__ void outproj_kernel(const float* __restrict__ Wo,
                               const float* __restrict__ bo,
                               float* __restrict__ out) {
    const int r = blockIdx.x;                       // 0..1023
    const int warp = threadIdx.x >> 5, lane = threadIdx.x & 31;
    const int c4 = warp*32 + lane;

    const float4 w4 = ((const float4*)(Wo + (size_t)r * ND))[c4];
    const float4* cp = (const float4*)g_ctx;

    float acc[NB];
#pragma unroll
    for (int b = 0; b < NB; ++b) {
        const float4 c4v = cp[b*(ND/4) + c4];
        acc[b] = w4.x*c4v.x + w4.y*c4v.y + w4.z*c4v.z + w4.w*c4v.w;
    }
#pragma unroll
    for (int b = 0; b < NB; ++b) {
#pragma unroll
        for (int o = 16; o; o >>= 1) acc[b] += __shfl_xor_sync(0xffffffffu, acc[b], o);
    }
    __shared__ float sm[8][NB+1];
    if (lane == 0) {
#pragma unroll
        for (int b = 0; b < NB; ++b) sm[warp][b] = acc[b];
    }
    __syncthreads();
    if (threadIdx.x < NB) {
        const int b = threadIdx.x;
        float v = sm[0][b];
#pragma unroll
        for (int w = 1; w < 8; ++w) v += sm[w][b];
        out[b*ND + r] = v + bo[r];
    }
}

// ---------------------------------------------------------------------------
extern "C" void kernel_launch(void* const* d_in, const int* in_sizes, int n_in,
                              void* d_out, int out_size) {
    const float* x      = (const float*)d_in[0];
    const float* Wq     = (const float*)d_in[1];
    const float* bq     = (const float*)d_in[2];
    const float* Wk     = (const float*)d_in[3];
    const float* bk     = (const float*)d_in[4];
    const float* Wv     = (const float*)d_in[5];
    const float* bv     = (const float*)d_in[6];
    const float* Wo     = (const float*)d_in[7];
    const float* bo     = (const float*)d_in[8];
    const float* past_k = (const float*)d_in[9];
    const float* past_v = (const float*)d_in[10];
    float* out = (float*)d_out;

    // One-time side stream + fork/join events (host objects only; no device mem).
    static cudaStream_t s_side = nullptr;
    static cudaEvent_t  e_fork = nullptr, e_join = nullptr;
    if (s_side == nullptr) {
        cudaStreamCreateWithFlags(&s_side, cudaStreamNonBlocking);
        cudaEventCreateWithFlags(&e_fork, cudaEventDisableTiming);
        cudaEventCreateWithFlags(&e_join, cudaEventDisableTiming);
    }

    // Fork: side stream projects K/V overlapped with the DRAM-bound scan.
    cudaEventRecord(e_fork, 0);
    cudaStreamWaitEvent(s_side, e_fork, 0);

    proj_q_kernel<<<ND, 256>>>(x, Wq, bq);                          // main
    proj_kv_kernel<<<2*ND, 256, 0, s_side>>>(x, Wk, bk, Wv, bv);    // side
    attn_partial<<<dim3(NCHUNK, NBH), 256>>>(past_k, past_v);       // main

    // Join: reduce needs k_new/v_new from the side stream.
    cudaEventRecord(e_join, s_side);
    cudaStreamWaitEvent(0, e_join, 0);

    attn_reduce<<<NBH, 256>>>();
    outproj_kernel<<<ND, 256>>>(Wo, bo, out);
}